// round 5
// baseline (speedup 1.0000x reference)
#include <cuda_runtime.h>
#include <cstdint>

// USR_EMB: out[row] = emb[searchsorted(userlist, x[row])], 64 f32/row.
// R4 post-mortem: ~88% of measured LTS cap (~12.3TB/s); residual is exposed
// latency + half-idle index phase. R5: 32 rows/warp (all lanes compute
// indices), 16 rows/thread software-pipelined in 4x4 batches (prefetch next
// gather batch before storing current), tail-free fast path, streaming hints
// keep the 25.6MB emb table L2-resident under the 210MB write stream.

static constexpr int EMB = 64;
static constexpr int CPR = EMB / 4;  // 16 float4 chunks per row
static constexpr int RPW = 32;       // rows per warp
static constexpr int RPT = 16;       // rows per thread (per 16-lane half)

__global__ void __launch_bounds__(256) usr_emb_kernel(
    const int* __restrict__ x,
    const int* __restrict__ userlist,
    const float4* __restrict__ emb,      // [emb_rows][16] float4
    float4* __restrict__ out,            // [n_rows][16] float4
    int n_rows, int n_userlist, int emb_rows)
{
    int warpId = (blockIdx.x * blockDim.x + threadIdx.x) >> 5;
    int lane   = threadIdx.x & 31;
    int group  = lane >> 4;              // which 16-row half this thread stores
    int chunk  = lane & 15;              // float4 within row
    int wrow0  = warpId * RPW;
    if (wrow0 >= n_rows) return;

    bool full = (wrow0 + RPW) <= n_rows;

    // ---- Cooperative index computation: all 32 lanes, one row each ----
    int r_me = wrow0 + lane;
    int u = (full || r_me < n_rows) ? __ldcs(&x[r_me]) : 0;  // coalesced 128B
    // Fast path: userlist = [-1, 0..N-1] => searchsorted(u) = u+1.
    // Verified against data; binary-search fallback for generality.
    int myIdx = u + 1;
    bool ok = (myIdx >= 1) && (myIdx < n_userlist)
              && (__ldg(&userlist[myIdx]) == u)
              && (__ldg(&userlist[myIdx - 1]) < u);
    if (!ok) {
        int lo = 0, hi = n_userlist;
        while (lo < hi) {
            int mid = (lo + hi) >> 1;
            if (__ldg(&userlist[mid]) < u) lo = mid + 1; else hi = mid;
        }
        myIdx = lo;
    }
    if (myIdx >= emb_rows) myIdx = emb_rows - 1;
    if (myIdx < 0) myIdx = 0;
    __syncwarp();

    // Each thread pulls its 16 row-indices from the computing lanes.
    int idx[RPT];
#pragma unroll
    for (int k = 0; k < RPT; k++)
        idx[k] = __shfl_sync(0xffffffffu, myIdx, group * RPT + k);

    int rowBase = wrow0 + group * RPT;

    if (full) {
        // ---- Pipelined: prefetch batch b+1 gathers, then store batch b ----
        float4 v[4];
#pragma unroll
        for (int k = 0; k < 4; k++)
            v[k] = __ldg(&emb[(size_t)idx[k] * CPR + chunk]);
#pragma unroll
        for (int b = 0; b < 4; b++) {
            float4 nxt[4];
            if (b < 3) {
#pragma unroll
                for (int k = 0; k < 4; k++)
                    nxt[k] = __ldg(&emb[(size_t)idx[(b + 1) * 4 + k] * CPR + chunk]);
            }
#pragma unroll
            for (int k = 0; k < 4; k++)
                __stcs(&out[(size_t)(rowBase + b * 4 + k) * CPR + chunk], v[k]);
            if (b < 3) {
#pragma unroll
                for (int k = 0; k < 4; k++) v[k] = nxt[k];
            }
        }
    } else {
        // Guarded tail path (generic shapes).
#pragma unroll
        for (int b = 0; b < 4; b++) {
            float4 v[4];
#pragma unroll
            for (int k = 0; k < 4; k++) {
                int r = rowBase + b * 4 + k;
                v[k] = (r < n_rows) ? __ldg(&emb[(size_t)idx[b * 4 + k] * CPR + chunk])
                                    : make_float4(0.f, 0.f, 0.f, 0.f);
            }
#pragma unroll
            for (int k = 0; k < 4; k++) {
                int r = rowBase + b * 4 + k;
                if (r < n_rows)
                    __stcs(&out[(size_t)r * CPR + chunk], v[k]);
            }
        }
    }
}

extern "C" void kernel_launch(void* const* d_in, const int* in_sizes, int n_in,
                              void* d_out, int out_size)
{
    const int*   x        = (const int*)d_in[0];    // [B*H] int32
    const int*   userlist = (const int*)d_in[1];    // [N+1] int32
    const float* emb      = (const float*)d_in[2];  // [(N+1)*64] f32

    int n_rows     = in_sizes[0];          // 819200
    int n_userlist = in_sizes[1];          // 100001
    int emb_rows   = in_sizes[2] / EMB;    // 100001

    int n_warps = (n_rows + RPW - 1) / RPW;          // 25600
    long long total_threads = (long long)n_warps * 32;
    int block = 256;
    int grid  = (int)((total_threads + block - 1) / block);  // 3200

    usr_emb_kernel<<<grid, block>>>(x, userlist, (const float4*)emb,
                                    (float4*)d_out, n_rows, n_userlist, emb_rows);
}